// round 16
// baseline (speedup 1.0000x reference)
#include <cuda_runtime.h>
#include <cuda_bf16.h>
#include <math.h>

// Problem dims (fixed by setup_inputs)
#define BB 64
#define KK 8
#define FF 24
#define DD 32   // KK + FF
#define HH 64
#define LL 2048
#define CC 64
#define XAUG_ELEMS (BB * LL * CC)   // 8388608

#define APPLY_TPB   512
#define NUM_CHUNKS  2048            // 64 batches * 32 chunks; chunk = 1024 float4
#define PERSIST_CTAS (148 * 4)      // one full wave at 4 CTAs/SM

// Per-batch selected transform + its intensity (scratch; no allocation allowed)
__device__ int   g_sel_k[BB];
__device__ float g_sel_t[BB];

// ---------------------------------------------------------------------------
// Kernel 1: per-batch dual MLP, split-K across 256 threads, all weight loads
// register-prefetched at entry. Fires PDL trigger before tail outputs.
// (Proven in R12 — unchanged.)
// ---------------------------------------------------------------------------
__global__ void __launch_bounds__(256) setup_kernel(
    const float* __restrict__ prev_prob,   // (B,K)
    const float* __restrict__ features,    // (B,F)
    const float* __restrict__ gumbel,      // (B,K)
    const float* __restrict__ pW1, const float* __restrict__ pb1,
    const float* __restrict__ pW2, const float* __restrict__ pb2,
    const float* __restrict__ pW3, const float* __restrict__ pb3,
    const float* __restrict__ iW1, const float* __restrict__ ib1,
    const float* __restrict__ iW2, const float* __restrict__ ib2,
    const float* __restrict__ iW3, const float* __restrict__ ib3,
    float* __restrict__ out_prob,          // (B,K)
    float* __restrict__ out_int,           // (B,K)
    float* __restrict__ out_sel)           // (B,)
{
    const int b   = blockIdx.x;
    const int tid = threadIdx.x;           // 0..255

    const int  neu  = tid & 127;
    const int  half = tid >> 7;
    const int  lt   = neu & 63;
    const bool isP  = (neu < 64);
    const int  mlp  = isP ? 0 : 1;

    const int  neu3  = tid >> 4;
    const int  part3 = tid & 15;
    const bool isP3  = (neu3 < 8);
    const int  k3    = neu3 & 7;

    __shared__ float s_in[DD];
    __shared__ float s_gum[KK];
    __shared__ float part[256];
    __shared__ float h1[2][HH];
    __shared__ float h2[2][HH];
    __shared__ float s_logit[KK];
    __shared__ float s_int[KK];

    // ---- front-issue everything (input + all weight slices) ----
    if (tid < KK)            s_in[tid] = prev_prob[b * KK + tid];
    else if (tid < DD)       s_in[tid] = features[b * FF + (tid - KK)];
    else if (tid < DD + KK)  s_gum[tid - DD] = gumbel[b * KK + (tid - DD)];

    float w1r[16];
    {
        const float* W1 = isP ? pW1 : iW1;
        const int i0 = half * 16;
        #pragma unroll
        for (int i = 0; i < 16; i++) w1r[i] = W1[(i0 + i) * HH + lt];
    }
    float w2r[32];
    {
        const float* W2 = isP ? pW2 : iW2;
        const int i0 = half * 32;
        #pragma unroll
        for (int i = 0; i < 32; i++) w2r[i] = W2[(i0 + i) * HH + lt];
    }
    float w3r[4];
    {
        const float* W3 = isP3 ? pW3 : iW3;
        const int i0 = part3 * 4;
        #pragma unroll
        for (int i = 0; i < 4; i++) w3r[i] = W3[(i0 + i) * KK + k3];
    }
    const float b1v = (tid < 128) ? (isP ? pb1 : ib1)[lt] : 0.f;
    const float b2v = (tid < 128) ? (isP ? pb2 : ib2)[lt] : 0.f;
    const float b3v = (part3 == 0) ? (isP3 ? pb3 : ib3)[k3] : 0.f;
    __syncthreads();

    // ---- layer 1: 32 inputs, split 16+16 ----
    {
        const int i0 = half * 16;
        float a = 0.f;
        #pragma unroll
        for (int i = 0; i < 16; i++) a = fmaf(s_in[i0 + i], w1r[i], a);
        part[tid] = a;
    }
    __syncthreads();
    if (tid < 128)
        h1[mlp][lt] = fmaxf(part[tid] + part[tid + 128] + b1v, 0.f);
    __syncthreads();

    // ---- layer 2: 64 inputs, split 32+32 ----
    {
        const float* h  = h1[mlp];
        const int i0 = half * 32;
        float a = 0.f;
        #pragma unroll
        for (int i = 0; i < 32; i++) a = fmaf(h[i0 + i], w2r[i], a);
        part[tid] = a;
    }
    __syncthreads();
    if (tid < 128)
        h2[mlp][lt] = fmaxf(part[tid] + part[tid + 128] + b2v, 0.f);
    __syncthreads();

    // ---- layer 3: 16 neurons x 16 threads, shfl-tree reduce ----
    {
        const unsigned grp_mask = 0xffffu << (((tid & 31) >> 4) << 4);
        const float* h = h2[isP3 ? 0 : 1];
        const int i0 = part3 * 4;
        float a = 0.f;
        #pragma unroll
        for (int i = 0; i < 4; i++) a = fmaf(h[i0 + i], w3r[i], a);
        a += __shfl_down_sync(grp_mask, a, 8, 16);
        a += __shfl_down_sync(grp_mask, a, 4, 16);
        a += __shfl_down_sync(grp_mask, a, 2, 16);
        a += __shfl_down_sync(grp_mask, a, 1, 16);
        if (part3 == 0) {
            a += b3v;
            if (isP3) s_logit[k3] = a;
            else      s_int[k3]   = (a > 20.f) ? a : log1pf(expf(a)); // softplus
        }
    }
    __syncthreads();

    if (tid == 0) {
        // argmax(logits + gumbel) == argmax(y_soft); selection is exactly
        // one-hot (y_hard + y_soft - stop_grad(y_soft) == y_hard numerically).
        int best = 0;
        float bv = s_logit[0] + s_gum[0];
        #pragma unroll
        for (int k = 1; k < KK; k++) {
            float v = s_logit[k] + s_gum[k];
            if (v > bv) { bv = v; best = k; }
        }
        g_sel_k[b] = best;
        g_sel_t[b] = s_int[best];
        out_sel[b] = (float)best;
    }
    __syncthreads();
#if __CUDA_ARCH__ >= 900
    cudaTriggerProgrammaticLaunchCompletion();
#endif

    // ---- tail outputs (after trigger; off everyone's critical path) ----
    if (tid == 0) {
        float m = s_logit[0];
        #pragma unroll
        for (int k = 1; k < KK; k++) m = fmaxf(m, s_logit[k]);
        float e[KK]; float sum = 0.f;
        #pragma unroll
        for (int k = 0; k < KK; k++) { e[k] = expf(s_logit[k] - m); sum += e[k]; }
        float inv = 1.f / sum;
        #pragma unroll
        for (int k = 0; k < KK; k++) out_prob[b * KK + k] = e[k] * inv;
        #pragma unroll
        for (int k = 0; k < KK; k++) out_int[b * KK + k] = s_int[k];
    }
}

// ---------------------------------------------------------------------------
// Kernel 2: PERSISTENT single-wave apply. 592 CTAs (148 SMs x 4) x 512 thr,
// grid-stride over 2048 chunks (chunk = 1024 float4 = half a batch row set).
// Eliminates wave-transition overhead of the 3.5-wave launch; the PDL wait is
// paid once per resident CTA. Chunk c -> batch b = c>>5, slice = c&31.
// Loads are k-independent (k==7 flip applied on the store side); per-chunk
// g_sel reads are L1-hits after the first iteration.
// ---------------------------------------------------------------------------
__global__ void __launch_bounds__(APPLY_TPB) apply_kernel(
    const float* __restrict__ x, float* __restrict__ out)
{
    const int tid = threadIdx.x;

    // First chunk's loads issued BEFORE the dependency wait (k-independent).
    int c0 = blockIdx.x;
    {
        const int b0    = c0 >> 5;
        const int base0 = ((c0 & 31) << 10) + tid;
        const float4* xi0 = (const float4*)x + ((size_t)b0 << 15);
        float4 v0 = xi0[base0];
        float4 v1 = xi0[base0 + 512];

#if __CUDA_ARCH__ >= 900
        cudaGridDependencySynchronize();   // wait for setup; makes g_sel visible
#endif

        for (int c = c0; ; ) {
            const int b    = c >> 5;
            const int base = ((c & 31) << 10) + tid;
            float4* oo = (float4*)out + ((size_t)b << 15);

            const int   k = g_sel_k[b];
            const float t = g_sel_t[b];

            if (k == 7) {
                int i0 = base, i1 = base + 512;
                oo[((LL - 1 - (i0 >> 4)) << 4) + (i0 & 15)] = v0;
                oo[((LL - 1 - (i1 >> 4)) << 4) + (i1 & 15)] = v1;
            } else if (k == 4) {
                const float A = 1.f + t;
                float4 w0 = v0, w1 = v1;
                w0.x = tanhf(w0.x * A); w0.y = tanhf(w0.y * A);
                w0.z = tanhf(w0.z * A); w0.w = tanhf(w0.w * A);
                w1.x = tanhf(w1.x * A); w1.y = tanhf(w1.y * A);
                w1.z = tanhf(w1.z * A); w1.w = tanhf(w1.w * A);
                oo[base] = w0; oo[base + 512] = w1;
            } else if (k == 6) {
                float4 w0 = v0, w1 = v1;
                w0.x = fmaf(t, sinf(w0.x), w0.x); w0.y = fmaf(t, sinf(w0.y), w0.y);
                w0.z = fmaf(t, sinf(w0.z), w0.z); w0.w = fmaf(t, sinf(w0.w), w0.w);
                w1.x = fmaf(t, sinf(w1.x), w1.x); w1.y = fmaf(t, sinf(w1.y), w1.y);
                w1.z = fmaf(t, sinf(w1.z), w1.z); w1.w = fmaf(t, sinf(w1.w), w1.w);
                oo[base] = w0; oo[base + 512] = w1;
            } else {
                float A = 1.f, Bc = 0.f;
                if      (k == 1) A = 1.f + t;
                else if (k == 2) Bc = t;
                else if (k == 3) A = 1.f - t;
                else if (k == 5) A = expf(-t);
                float4 w0 = v0, w1 = v1;
                w0.x = fmaf(w0.x, A, Bc); w0.y = fmaf(w0.y, A, Bc);
                w0.z = fmaf(w0.z, A, Bc); w0.w = fmaf(w0.w, A, Bc);
                w1.x = fmaf(w1.x, A, Bc); w1.y = fmaf(w1.y, A, Bc);
                w1.z = fmaf(w1.z, A, Bc); w1.w = fmaf(w1.w, A, Bc);
                oo[base] = w0; oo[base + 512] = w1;
            }

            // prefetch next chunk (loads don't depend on the stores above)
            c += gridDim.x;
            if (c >= NUM_CHUNKS) break;
            const int bn    = c >> 5;
            const int basen = ((c & 31) << 10) + tid;
            const float4* xin = (const float4*)x + ((size_t)bn << 15);
            v0 = xin[basen];
            v1 = xin[basen + 512];
        }
    }
}

extern "C" void kernel_launch(void* const* d_in, const int* in_sizes, int n_in,
                              void* d_out, int out_size)
{
    const float* x         = (const float*)d_in[0];
    const float* prev_prob = (const float*)d_in[1];
    const float* features  = (const float*)d_in[2];
    const float* gumbel    = (const float*)d_in[3];
    // d_in[4] = log_temperature: dead for forward values (exact one-hot selection;
    // tau>0 never changes the argmax; prob uses the raw softmax of logits).
    const float* pW1 = (const float*)d_in[5];
    const float* pb1 = (const float*)d_in[6];
    const float* pW2 = (const float*)d_in[7];
    const float* pb2 = (const float*)d_in[8];
    const float* pW3 = (const float*)d_in[9];
    const float* pb3 = (const float*)d_in[10];
    const float* iW1 = (const float*)d_in[11];
    const float* ib1 = (const float*)d_in[12];
    const float* iW2 = (const float*)d_in[13];
    const float* ib2 = (const float*)d_in[14];
    const float* iW3 = (const float*)d_in[15];
    const float* ib3 = (const float*)d_in[16];

    float* out      = (float*)d_out;
    float* out_prob = out + XAUG_ELEMS;              // (B,K)
    float* out_int  = out_prob + BB * KK;            // (B,K)
    float* out_sel  = out_int  + BB * KK;            // (B,)

    setup_kernel<<<BB, 256>>>(prev_prob, features, gumbel,
                              pW1, pb1, pW2, pb2, pW3, pb3,
                              iW1, ib1, iW2, ib2, iW3, ib3,
                              out_prob, out_int, out_sel);

    // Persistent apply kernel with Programmatic Dependent Launch.
    cudaLaunchConfig_t cfg = {};
    cfg.gridDim  = dim3(PERSIST_CTAS, 1, 1);
    cfg.blockDim = dim3(APPLY_TPB, 1, 1);
    cfg.dynamicSmemBytes = 0;
    cfg.stream = 0;
    cudaLaunchAttribute attr[1];
    attr[0].id = cudaLaunchAttributeProgrammaticStreamSerialization;
    attr[0].val.programmaticStreamSerializationAllowed = 1;
    cfg.attrs = attr;
    cfg.numAttrs = 1;
    cudaLaunchKernelEx(&cfg, apply_kernel, x, out);
}